// round 3
// baseline (speedup 1.0000x reference)
#include <cuda_runtime.h>
#include <cuda_fp16.h>
#include <math.h>

#define S       64
#define LPREV   512
#define NF      193
#define NFRAMES 100
#define BATCH   64
#define NTH     256
#define NBT     (BATCH * NFRAMES)   // 6400
#define PADFW   416                 // Wfw in_dim 388 padded to 416 (52 uint4 chunks)

// ---------------- scratch (static device allocations) ----------------
__device__ float  g_X [NBT * 256];
__device__ float  g_H1[NBT * 256];
__device__ float  g_H2[NBT * 256];
__device__ float  g_C [NBT * 512];
__device__ int    g_period[NBT];
__device__ __half g_hWsd[128 * 320];

__device__ __forceinline__ float sigm(float x) { return 1.0f / (1.0f + __expf(-x)); }

// ---------------- prep: fp16 conversion of Wsd ----------------
__global__ void convert_wsd_kernel(const float* __restrict__ Wsd)
{
    int i = blockIdx.x * blockDim.x + threadIdx.x;
    if (i < 128 * 320) g_hWsd[i] = __float2half(Wsd[i]);
}

// ---------------- conditioning precompute ----------------
__global__ void build_x_kernel(const float* __restrict__ feats,
                               const float* __restrict__ glob)
{
    const int bt = blockIdx.x;
    const int b = bt / NFRAMES, t = bt % NFRAMES;
    const float* fb = feats + (long)b * NF * NFRAMES;
    for (int i = threadIdx.x; i < 192; i += blockDim.x)
        g_X[bt * 256 + i] = fb[i * NFRAMES + t];
    for (int i = threadIdx.x; i < 64; i += blockDim.x)
        g_X[bt * 256 + 192 + i] = glob[b * 64 + i];
    if (threadIdx.x == 0)
        g_period[bt] = (int)lrintf(fb[192 * NFRAMES + t]);
}

// C[M,N] = tanh(A[M,K] @ W[N,K]^T); M=6400, K=256, N in {256,512}; tiles 64x64x64
__global__ __launch_bounds__(256)
void gemm_tanh_kernel(const float* __restrict__ Wt, int layer, int N, int K)
{
    const float* A = (layer == 0) ? g_X : (layer == 1) ? g_H1 : g_H2;
    float*       C = (layer == 0) ? g_H1 : (layer == 1) ? g_H2 : g_C;

    __shared__ float As[64][68];
    __shared__ float Ws[64][68];

    const int tid = threadIdx.x;
    const int m0 = blockIdx.y * 64, n0 = blockIdx.x * 64;
    const int lr = tid >> 2, lc = tid & 3;
    const int ty = tid >> 4, tx = tid & 15;

    float acc[4][4] = {};

    for (int k0 = 0; k0 < K; k0 += 64) {
        const float4* Arow = (const float4*)(A  + (long)(m0 + lr) * K + k0);
        const float4* Wrow = (const float4*)(Wt + (long)(n0 + lr) * K + k0);
        #pragma unroll
        for (int jj = 0; jj < 4; jj++) {
            float4 av = __ldg(&Arow[lc * 4 + jj]);
            float4 wv = __ldg(&Wrow[lc * 4 + jj]);
            int kk = lc * 16 + jj * 4;
            As[kk + 0][lr] = av.x; As[kk + 1][lr] = av.y;
            As[kk + 2][lr] = av.z; As[kk + 3][lr] = av.w;
            Ws[kk + 0][lr] = wv.x; Ws[kk + 1][lr] = wv.y;
            Ws[kk + 2][lr] = wv.z; Ws[kk + 3][lr] = wv.w;
        }
        __syncthreads();
        #pragma unroll
        for (int kk = 0; kk < 64; kk++) {
            float4 a = *(const float4*)&As[kk][ty * 4];
            float4 w = *(const float4*)&Ws[kk][tx * 4];
            acc[0][0] = fmaf(a.x, w.x, acc[0][0]); acc[0][1] = fmaf(a.x, w.y, acc[0][1]);
            acc[0][2] = fmaf(a.x, w.z, acc[0][2]); acc[0][3] = fmaf(a.x, w.w, acc[0][3]);
            acc[1][0] = fmaf(a.y, w.x, acc[1][0]); acc[1][1] = fmaf(a.y, w.y, acc[1][1]);
            acc[1][2] = fmaf(a.y, w.z, acc[1][2]); acc[1][3] = fmaf(a.y, w.w, acc[1][3]);
            acc[2][0] = fmaf(a.z, w.x, acc[2][0]); acc[2][1] = fmaf(a.z, w.y, acc[2][1]);
            acc[2][2] = fmaf(a.z, w.z, acc[2][2]); acc[2][3] = fmaf(a.z, w.w, acc[2][3]);
            acc[3][0] = fmaf(a.w, w.x, acc[3][0]); acc[3][1] = fmaf(a.w, w.y, acc[3][1]);
            acc[3][2] = fmaf(a.w, w.z, acc[3][2]); acc[3][3] = fmaf(a.w, w.w, acc[3][3]);
        }
        __syncthreads();
    }
    #pragma unroll
    for (int i = 0; i < 4; i++)
        #pragma unroll
        for (int j = 0; j < 4; j++)
            C[(long)(m0 + ty * 4 + i) * N + n0 + tx * 4 + j] = tanhf(acc[i][j]);
}

// ---------------- fp16 matvec helpers ----------------

// accumulate 8 halves (one uint4) against 8 fp32 inputs
__device__ __forceinline__ void fma8(float& acc, uint4 u, const float4* x2, int j)
{
    __half2 h0 = *reinterpret_cast<__half2*>(&u.x);
    __half2 h1 = *reinterpret_cast<__half2*>(&u.y);
    __half2 h2 = *reinterpret_cast<__half2*>(&u.z);
    __half2 h3 = *reinterpret_cast<__half2*>(&u.w);
    float2 f0 = __half22float2(h0), f1 = __half22float2(h1);
    float2 f2 = __half22float2(h2), f3 = __half22float2(h3);
    float4 xa = x2[2 * j], xb = x2[2 * j + 1];
    acc = fmaf(f0.x, xa.x, acc); acc = fmaf(f0.y, xa.y, acc);
    acc = fmaf(f1.x, xa.z, acc); acc = fmaf(f1.y, xa.w, acc);
    acc = fmaf(f2.x, xb.x, acc); acc = fmaf(f2.y, xb.y, acc);
    acc = fmaf(f3.x, xb.z, acc); acc = fmaf(f3.y, xb.w, acc);
}

// smem fp16 weight matvec: 4 thr/row, in_dim % 32 == 0
__device__ __forceinline__ void matvec_sh(const __half* W,
                                          const float* __restrict__ vin,
                                          float* __restrict__ vout,
                                          int out_dim, int in_dim, int act)
{
    const int t = threadIdx.x, p = t & 3, r0 = t >> 2;
    const int nchunk = in_dim >> 3;   // uint4 chunks of 8 halves
    const float4* x2 = reinterpret_cast<const float4*>(vin);
    for (int row = r0; row < out_dim; row += (NTH / 4)) {
        const uint4* w = reinterpret_cast<const uint4*>(W + row * in_dim);
        float acc = 0.f;
        #pragma unroll 4
        for (int j = p; j < nchunk; j += 4)
            fma8(acc, w[j], x2, j);
        acc += __shfl_xor_sync(0xffffffffu, acc, 1);
        acc += __shfl_xor_sync(0xffffffffu, acc, 2);
        if (p == 0) vout[row] = (act == 1) ? tanhf(acc) : acc;
    }
}

// global fp16 weight matvec (Wsd)
__device__ __forceinline__ void matvec_gh(const __half* __restrict__ W,
                                          const float* __restrict__ vin,
                                          float* __restrict__ vout,
                                          int out_dim, int in_dim, int act)
{
    const int t = threadIdx.x, p = t & 3, r0 = t >> 2;
    const int nchunk = in_dim >> 3;
    const float4* x2 = reinterpret_cast<const float4*>(vin);
    for (int row = r0; row < out_dim; row += (NTH / 4)) {
        const uint4* w = reinterpret_cast<const uint4*>(W + row * in_dim);
        float acc = 0.f;
        #pragma unroll 4
        for (int j = p; j < nchunk; j += 4)
            fma8(acc, __ldg(&w[j]), x2, j);
        acc += __shfl_xor_sync(0xffffffffu, acc, 1);
        acc += __shfl_xor_sync(0xffffffffu, acc, 2);
        if (p == 0) vout[row] = (act == 1) ? tanhf(acc) : acc;
    }
}

// fp32 -> fp16 smem copy (one-time)
__device__ __forceinline__ void copy_h(__half* dst, const float* __restrict__ src, int n)
{
    for (int i = threadIdx.x; i < (n >> 1); i += NTH) {
        float2 v = __ldg((const float2*)src + i);
        reinterpret_cast<__half2*>(dst)[i] = __floats2half2_rn(v.x, v.y);
    }
}

#define DYN_HALFS (64 * PADFW + 3 * 192 * 128)   // Wfw + Wih1..3
#define DYN_BYTES (DYN_HALFS * 2)                // 200704 B

__global__ __launch_bounds__(NTH, 1)
void fargan_kernel(const float* __restrict__ prev0,
                   const float* __restrict__ Wfw,     // (64,388)
                   const float* __restrict__ Wfw_g,   // (64,64)
                   const float* __restrict__ Wih1,    // (192,128)
                   const float* __restrict__ Whh1,    // (192,64)
                   const float* __restrict__ Wih2,
                   const float* __restrict__ Whh2,
                   const float* __restrict__ Wih3,
                   const float* __restrict__ Whh3,
                   const float* __restrict__ Wg1,     // (64,64)
                   const float* __restrict__ Wg2,
                   const float* __restrict__ Wg3,
                   const float* __restrict__ Wsg,     // (128,128)
                   const float* __restrict__ Wout,    // (64,128)
                   float* __restrict__ outp)          // (B, 25600)
{
    const int b   = blockIdx.x;
    const int tid = threadIdx.x;
    const int p   = tid & 3;
    const int r0  = tid >> 2;

    extern __shared__ __half dynh[];
    __half* sWfw  = dynh;                       // 64 x 416
    __half* sWih1 = dynh + 64 * PADFW;          // 192 x 128
    __half* sWih2 = sWih1 + 192 * 128;
    __half* sWih3 = sWih2 + 192 * 128;

    __shared__ __align__(16) float ring[LPREV];
    __shared__ __align__(16) float st1[S], st2[S], st3[S];
    __shared__ __align__(16) float sfw[2 * S];
    __shared__ __align__(16) float cframe[512];
    __shared__ __align__(16) float subin[PADFW];
    __shared__ __align__(16) float gi[3 * S];
    __shared__ __align__(16) float gh[3 * S];
    __shared__ __align__(16) float psub[S];
    __shared__ __align__(16) float fwv[S];
    __shared__ __align__(16) float xcat[2 * S];
    __shared__ __align__(16) float o1v[S], o2v[S];
    __shared__ __align__(16) float skip[5 * S];
    __shared__ __align__(16) float sdv[2 * S];
    __shared__ __align__(16) float sov[2 * S];
    __shared__ __align__(16) float gg[2 * S];
    __shared__ __align__(16) float outv[S];

    // ---- one-time: convert big weights into smem fp16 ----
    for (int i = tid; i < 64 * PADFW; i += NTH) {
        int row = i / PADFW, col = i % PADFW;
        sWfw[i] = (col < 388) ? __float2half(__ldg(&Wfw[row * 388 + col])) : __half(0.f);
    }
    copy_h(sWih1, Wih1, 192 * 128);
    copy_h(sWih2, Wih2, 192 * 128);
    copy_h(sWih3, Wih3, 192 * 128);

    // ---- register fp16 caches (each thread holds exactly its matvec slice) ----
    // Whh (192x64): rows r0+64*it, elems [p*16, p*16+16)
    __half2 rWhh[3][3][8];
    {
        const float* Ws[3] = { Whh1, Whh2, Whh3 };
        #pragma unroll
        for (int m = 0; m < 3; m++)
            #pragma unroll
            for (int it = 0; it < 3; it++) {
                const float* wr = Ws[m] + (r0 + 64 * it) * 64 + p * 16;
                #pragma unroll
                for (int jj = 0; jj < 8; jj++)
                    rWhh[m][it][jj] = __floats2half2_rn(__ldg(&wr[2 * jj]), __ldg(&wr[2 * jj + 1]));
            }
    }
    // Wg1..3 + Wfwg (64x64): row r0, elems [p*16, p*16+16)
    __half2 rWg[4][8];
    {
        const float* Ws[4] = { Wg1, Wg2, Wg3, Wfw_g };
        #pragma unroll
        for (int m = 0; m < 4; m++) {
            const float* wr = Ws[m] + r0 * 64 + p * 16;
            #pragma unroll
            for (int jj = 0; jj < 8; jj++)
                rWg[m][jj] = __floats2half2_rn(__ldg(&wr[2 * jj]), __ldg(&wr[2 * jj + 1]));
        }
    }
    // Wsg (128x128): rows r0+64*it, elems [p*32, p*32+32)
    __half2 rsg[2][16];
    #pragma unroll
    for (int it = 0; it < 2; it++) {
        const float* wr = Wsg + (r0 + 64 * it) * 128 + p * 32;
        #pragma unroll
        for (int jj = 0; jj < 16; jj++)
            rsg[it][jj] = __floats2half2_rn(__ldg(&wr[2 * jj]), __ldg(&wr[2 * jj + 1]));
    }
    // Wout (64x128): row r0, elems [p*32, p*32+32)
    __half2 rout[16];
    {
        const float* wr = Wout + r0 * 128 + p * 32;
        #pragma unroll
        for (int jj = 0; jj < 16; jj++)
            rout[jj] = __floats2half2_rn(__ldg(&wr[2 * jj]), __ldg(&wr[2 * jj + 1]));
    }

    // ---- init state ----
    for (int i = tid; i < LPREV; i += NTH) ring[i] = prev0[b * LPREV + i];
    if (tid < S) { st1[tid] = 0.f; st2[tid] = 0.f; st3[tid] = 0.f; }
    for (int i = tid; i < 2 * S; i += NTH) sfw[i] = 0.f;
    if (tid < PADFW - 388) subin[388 + tid] = 0.f;   // pad zeros, written once
    int head = 0;
    __syncthreads();

    for (int tf = 0; tf < NFRAMES; tf++) {
        const int bt = b * NFRAMES + tf;
        {   // conditioning row precomputed
            const float4* s = (const float4*)(g_C + (long)bt * 512);
            float4* d = (float4*)cframe;
            for (int i = tid; i < 128; i += NTH) d[i] = __ldg(&s[i]);
        }
        __syncthreads();
        const int period = g_period[bt];

        for (int k = 0; k < 4; k++) {
            // ---- subframe input: [feat2s(128) | prev_sub(64) | lookback(68) | sfw(128)]
            for (int m = tid; m < 128; m += NTH) subin[m] = cframe[4 * m + k];
            if (tid < 64) {
                float v = ring[(head + 448 + tid) & 511];
                subin[128 + tid] = v;
                psub[tid] = v;
            }
            if (tid < 68) {
                int idx = LPREV - period + tid - 2;
                if (idx >= LPREV) idx -= period;
                subin[192 + tid] = ring[(head + idx) & 511];
            }
            for (int i = tid; i < 128; i += NTH) subin[260 + i] = sfw[i];
            __syncthreads();

            // ---- fw = GLU(tanh(subin @ Wfw.T), Wfw_g)
            matvec_sh(sWfw, subin, fwv, 64, PADFW, 1); __syncthreads();
            {   // gg = fwv @ Wfwg.T (register fp16 weights)
                float acc = 0.f;
                #pragma unroll
                for (int jj = 0; jj < 8; jj++) {
                    float2 w = __half22float2(rWg[3][jj]);
                    acc = fmaf(w.x, fwv[p * 16 + 2 * jj],     acc);
                    acc = fmaf(w.y, fwv[p * 16 + 2 * jj + 1], acc);
                }
                acc += __shfl_xor_sync(0xffffffffu, acc, 1);
                acc += __shfl_xor_sync(0xffffffffu, acc, 2);
                if (p == 0) gg[r0] = acc;
            }
            __syncthreads();
            if (tid < 64) {
                float f2 = fwv[tid] * sigm(gg[tid]);
                fwv[tid] = f2;
                xcat[tid] = f2;
                xcat[64 + tid] = psub[tid];
            }
            __syncthreads();

            // ---- three GRU + GLU layers ----
            #pragma unroll
            for (int layer = 0; layer < 3; layer++) {
                const __half* sWih = (layer == 0) ? sWih1 : (layer == 1) ? sWih2 : sWih3;
                float* st = (layer == 0) ? st1 : (layer == 1) ? st2 : st3;

                matvec_sh(sWih, xcat, gi, 192, 128, 0);
                {   // gh = st @ Whh.T (register fp16)
                    #pragma unroll
                    for (int it = 0; it < 3; it++) {
                        float acc = 0.f;
                        #pragma unroll
                        for (int jj = 0; jj < 8; jj++) {
                            float2 w = __half22float2(rWhh[layer][it][jj]);
                            acc = fmaf(w.x, st[p * 16 + 2 * jj],     acc);
                            acc = fmaf(w.y, st[p * 16 + 2 * jj + 1], acc);
                        }
                        acc += __shfl_xor_sync(0xffffffffu, acc, 1);
                        acc += __shfl_xor_sync(0xffffffffu, acc, 2);
                        if (p == 0) gh[r0 + 64 * it] = acc;
                    }
                }
                __syncthreads();
                if (tid < 64) {
                    float r = sigm(gi[tid] + gh[tid]);
                    float z = sigm(gi[64 + tid] + gh[64 + tid]);
                    float n = tanhf(gi[128 + tid] + r * gh[128 + tid]);
                    st[tid] = (1.f - z) * n + z * st[tid];
                }
                __syncthreads();
                {   // gg = st @ Wg.T (register fp16)
                    float acc = 0.f;
                    #pragma unroll
                    for (int jj = 0; jj < 8; jj++) {
                        float2 w = __half22float2(rWg[layer][jj]);
                        acc = fmaf(w.x, st[p * 16 + 2 * jj],     acc);
                        acc = fmaf(w.y, st[p * 16 + 2 * jj + 1], acc);
                    }
                    acc += __shfl_xor_sync(0xffffffffu, acc, 1);
                    acc += __shfl_xor_sync(0xffffffffu, acc, 2);
                    if (p == 0) gg[r0] = acc;
                }
                __syncthreads();
                if (tid < 64) {
                    float v = st[tid] * sigm(gg[tid]);
                    if (layer == 0) o1v[tid] = v;
                    if (layer == 1) o2v[tid] = v;
                    if (layer == 2) {
                        skip[tid]       = o1v[tid];
                        skip[64 + tid]  = o2v[tid];
                        skip[128 + tid] = v;
                        skip[192 + tid] = fwv[tid];
                        skip[256 + tid] = psub[tid];
                    } else {
                        xcat[tid] = v;
                    }
                }
                __syncthreads();
            }

            // ---- skip head: sdv = tanh(skip @ Wsd.T) (L2-streamed fp16)
            matvec_gh(g_hWsd, skip, sdv, 128, 320, 1); __syncthreads();
            {   // gg = sdv @ Wsg.T (register fp16)
                #pragma unroll
                for (int it = 0; it < 2; it++) {
                    float acc = 0.f;
                    #pragma unroll
                    for (int jj = 0; jj < 16; jj++) {
                        float2 w = __half22float2(rsg[it][jj]);
                        acc = fmaf(w.x, sdv[p * 32 + 2 * jj],     acc);
                        acc = fmaf(w.y, sdv[p * 32 + 2 * jj + 1], acc);
                    }
                    acc += __shfl_xor_sync(0xffffffffu, acc, 1);
                    acc += __shfl_xor_sync(0xffffffffu, acc, 2);
                    if (p == 0) gg[r0 + 64 * it] = acc;
                }
            }
            __syncthreads();
            if (tid < 128) sov[tid] = sdv[tid] * sigm(gg[tid]);
            __syncthreads();
            {   // outv = tanh(sov @ Wout.T) (register fp16)
                float acc = 0.f;
                #pragma unroll
                for (int jj = 0; jj < 16; jj++) {
                    float2 w = __half22float2(rout[jj]);
                    acc = fmaf(w.x, sov[p * 32 + 2 * jj],     acc);
                    acc = fmaf(w.y, sov[p * 32 + 2 * jj + 1], acc);
                }
                acc += __shfl_xor_sync(0xffffffffu, acc, 1);
                acc += __shfl_xor_sync(0xffffffffu, acc, 2);
                if (p == 0) outv[r0] = tanhf(acc);
            }
            __syncthreads();

            // ---- emit, update ring + sfw
            if (tid < 64) {
                float v = outv[tid];
                outp[(long)b * (NFRAMES * 4 * S) + tf * (4 * S) + k * S + tid] = v;
                ring[(head + tid) & 511] = v;
            }
            for (int m = tid; m < 128; m += NTH) sfw[m] = cframe[4 * m + k];
            head = (head + 64) & 511;
            __syncthreads();
        }
    }
}

extern "C" void kernel_launch(void* const* d_in, const int* in_sizes, int n_in,
                              void* d_out, int out_size)
{
    const float* feats = (const float*)d_in[0];
    const float* glob  = (const float*)d_in[1];
    const float* prev0 = (const float*)d_in[2];
    const float* Wc1   = (const float*)d_in[3];
    const float* Wc2   = (const float*)d_in[4];
    const float* Wc3   = (const float*)d_in[5];
    const float* Wfw   = (const float*)d_in[6];
    const float* Wfw_g = (const float*)d_in[7];
    const float* Wih1  = (const float*)d_in[8];
    const float* Whh1  = (const float*)d_in[9];
    const float* Wih2  = (const float*)d_in[10];
    const float* Whh2  = (const float*)d_in[11];
    const float* Wih3  = (const float*)d_in[12];
    const float* Whh3  = (const float*)d_in[13];
    const float* Wg1   = (const float*)d_in[14];
    const float* Wg2   = (const float*)d_in[15];
    const float* Wg3   = (const float*)d_in[16];
    const float* Wsg   = (const float*)d_in[17];
    const float* Wsd   = (const float*)d_in[18];
    const float* Wout  = (const float*)d_in[19];
    float* outp = (float*)d_out;

    static bool attr_set = false;
    if (!attr_set) {
        cudaFuncSetAttribute(fargan_kernel,
                             cudaFuncAttributeMaxDynamicSharedMemorySize, DYN_BYTES);
        attr_set = true;
    }

    convert_wsd_kernel<<<(128 * 320 + 255) / 256, 256>>>(Wsd);
    build_x_kernel<<<NBT, 64>>>(feats, glob);
    gemm_tanh_kernel<<<dim3(4, 100), 256>>>(Wc1, 0, 256, 256);
    gemm_tanh_kernel<<<dim3(4, 100), 256>>>(Wc2, 1, 256, 256);
    gemm_tanh_kernel<<<dim3(8, 100), 256>>>(Wc3, 2, 512, 256);
    fargan_kernel<<<BATCH, NTH, DYN_BYTES>>>(prev0,
                                  Wfw, Wfw_g,
                                  Wih1, Whh1, Wih2, Whh2, Wih3, Whh3,
                                  Wg1, Wg2, Wg3, Wsg, Wout, outp);
}

// round 4
// speedup vs baseline: 1.3503x; 1.3503x over previous
#include <cuda_runtime.h>
#include <cuda_fp16.h>
#include <math.h>

#define S       64
#define LPREV   512
#define NF      193
#define NFRAMES 100
#define BATCH   64
#define NTH     512
#define NBT     (BATCH * NFRAMES)   // 6400

// ---------------- scratch (static device allocations) ----------------
__device__ float g_X [NBT * 256];
__device__ float g_H1[NBT * 256];
__device__ float g_H2[NBT * 256];
__device__ float g_C [NBT * 512];
__device__ float g_fwpre[NBT * 4 * 64];
__device__ int   g_period[NBT];

__device__ __forceinline__ float sigm(float x) { return 1.0f / (1.0f + __expf(-x)); }
__device__ __forceinline__ float hsum4(float4 a) { return (a.x + a.y) + (a.z + a.w); }
__device__ __forceinline__ float red8(float v) {
    v += __shfl_xor_sync(0xffffffffu, v, 1);
    v += __shfl_xor_sync(0xffffffffu, v, 2);
    v += __shfl_xor_sync(0xffffffffu, v, 4);
    return v;
}
__device__ __forceinline__ void fma4(float4& a, float4 w, float4 x) {
    a.x = fmaf(w.x, x.x, a.x); a.y = fmaf(w.y, x.y, a.y);
    a.z = fmaf(w.z, x.z, a.z); a.w = fmaf(w.w, x.w, a.w);
}
// dot of 8 fp16 weights (one uint4) with 8 fp32 inputs (two float4)
__device__ __forceinline__ float dot8h(uint4 u, float4 xa, float4 xb) {
    float2 f0 = __half22float2(*reinterpret_cast<__half2*>(&u.x));
    float2 f1 = __half22float2(*reinterpret_cast<__half2*>(&u.y));
    float2 f2 = __half22float2(*reinterpret_cast<__half2*>(&u.z));
    float2 f3 = __half22float2(*reinterpret_cast<__half2*>(&u.w));
    float a = fmaf(f0.x, xa.x, f0.y * xa.y);
    a = fmaf(f1.x, xa.z, a); a = fmaf(f1.y, xa.w, a);
    a = fmaf(f2.x, xb.x, a); a = fmaf(f2.y, xb.y, a);
    a = fmaf(f3.x, xb.z, a); a = fmaf(f3.y, xb.w, a);
    return a;
}

// ---------------- conditioning precompute ----------------
__global__ void build_x_kernel(const float* __restrict__ feats,
                               const float* __restrict__ glob)
{
    const int bt = blockIdx.x;
    const int b = bt / NFRAMES, t = bt % NFRAMES;
    const float* fb = feats + (long)b * NF * NFRAMES;
    for (int i = threadIdx.x; i < 192; i += blockDim.x)
        g_X[bt * 256 + i] = fb[i * NFRAMES + t];
    for (int i = threadIdx.x; i < 64; i += blockDim.x)
        g_X[bt * 256 + 192 + i] = glob[b * 64 + i];
    if (threadIdx.x == 0)
        g_period[bt] = (int)lrintf(fb[192 * NFRAMES + t]);
}

// C[M,N] = tanh(A[M,K] @ W[N,K]^T); tiles 64x64x64
__global__ __launch_bounds__(256)
void gemm_tanh_kernel(const float* __restrict__ Wt, int layer, int N, int K)
{
    const float* A = (layer == 0) ? g_X : (layer == 1) ? g_H1 : g_H2;
    float*       C = (layer == 0) ? g_H1 : (layer == 1) ? g_H2 : g_C;

    __shared__ float As[64][68];
    __shared__ float Ws[64][68];

    const int tid = threadIdx.x;
    const int m0 = blockIdx.y * 64, n0 = blockIdx.x * 64;
    const int lr = tid >> 2, lc = tid & 3;
    const int ty = tid >> 4, tx = tid & 15;

    float acc[4][4] = {};

    for (int k0 = 0; k0 < K; k0 += 64) {
        const float4* Arow = (const float4*)(A  + (long)(m0 + lr) * K + k0);
        const float4* Wrow = (const float4*)(Wt + (long)(n0 + lr) * K + k0);
        #pragma unroll
        for (int jj = 0; jj < 4; jj++) {
            float4 av = __ldg(&Arow[lc * 4 + jj]);
            float4 wv = __ldg(&Wrow[lc * 4 + jj]);
            int kk = lc * 16 + jj * 4;
            As[kk + 0][lr] = av.x; As[kk + 1][lr] = av.y;
            As[kk + 2][lr] = av.z; As[kk + 3][lr] = av.w;
            Ws[kk + 0][lr] = wv.x; Ws[kk + 1][lr] = wv.y;
            Ws[kk + 2][lr] = wv.z; Ws[kk + 3][lr] = wv.w;
        }
        __syncthreads();
        #pragma unroll
        for (int kk = 0; kk < 64; kk++) {
            float4 a = *(const float4*)&As[kk][ty * 4];
            float4 w = *(const float4*)&Ws[kk][tx * 4];
            acc[0][0] = fmaf(a.x, w.x, acc[0][0]); acc[0][1] = fmaf(a.x, w.y, acc[0][1]);
            acc[0][2] = fmaf(a.x, w.z, acc[0][2]); acc[0][3] = fmaf(a.x, w.w, acc[0][3]);
            acc[1][0] = fmaf(a.y, w.x, acc[1][0]); acc[1][1] = fmaf(a.y, w.y, acc[1][1]);
            acc[1][2] = fmaf(a.y, w.z, acc[1][2]); acc[1][3] = fmaf(a.y, w.w, acc[1][3]);
            acc[2][0] = fmaf(a.z, w.x, acc[2][0]); acc[2][1] = fmaf(a.z, w.y, acc[2][1]);
            acc[2][2] = fmaf(a.z, w.z, acc[2][2]); acc[2][3] = fmaf(a.z, w.w, acc[2][3]);
            acc[3][0] = fmaf(a.w, w.x, acc[3][0]); acc[3][1] = fmaf(a.w, w.y, acc[3][1]);
            acc[3][2] = fmaf(a.w, w.z, acc[3][2]); acc[3][3] = fmaf(a.w, w.w, acc[3][3]);
        }
        __syncthreads();
    }
    #pragma unroll
    for (int i = 0; i < 4; i++)
        #pragma unroll
        for (int j = 0; j < 4; j++)
            C[(long)(m0 + ty * 4 + i) * N + n0 + tx * 4 + j] = tanhf(acc[i][j]);
}

// fwpre[bt][k][j] = Wfw[j, 0:128] @ feat2s(bt,k) + Wfw[j, 260:388] @ sfw(bt,k)
// feat2s(bt,k)[m] = g_C[bt][4m+k]; sfw(bt,k) = feat2s of previous subframe (zeros at t=0,k=0)
__global__ __launch_bounds__(256)
void fwpre_kernel(const float* __restrict__ Wfw)
{
    const int bt = blockIdx.x;
    const int t  = bt % NFRAMES;
    const int tid = threadIdx.x;
    __shared__ float sc[512], sp[512];
    for (int i = tid; i < 512; i += 256) {
        sc[i] = g_C[(long)bt * 512 + i];
        sp[i] = (t > 0) ? g_C[(long)(bt - 1) * 512 + i] : 0.f;
    }
    __syncthreads();
    const int p = tid & 3, row = tid >> 2;
    const float* wr = Wfw + row * 388;
    #pragma unroll
    for (int k = 0; k < 4; k++) {
        // sfw for subframe k: k==0 -> prev frame's k=3 feat2s; else current frame k-1
        const float* sfw = (k == 0) ? sp : sc;
        const int ksf = (k == 0) ? 3 : (k - 1);
        float acc = 0.f;
        #pragma unroll 8
        for (int mm = 0; mm < 32; mm++) {
            int m = p * 32 + mm;
            acc = fmaf(__ldg(&wr[m]),       sc[4 * m + k],    acc);
            acc = fmaf(__ldg(&wr[260 + m]), sfw[4 * m + ksf], acc);
        }
        acc += __shfl_xor_sync(0xffffffffu, acc, 1);
        acc += __shfl_xor_sync(0xffffffffu, acc, 2);
        if (p == 0) g_fwpre[((long)bt * 4 + k) * 64 + row] = acc;
    }
}

// ---------------- serial recurrence ----------------

#define DYN_F32   (3 * 192 * 64 + 64 * 136)     // Whh x3 + Wfw2 = 45568 floats
#define DYN_H16   (4 * 64 * 64)                 // Wg1..3 + Wfwg = 16384 halfs
#define DYN_BYTES (DYN_F32 * 4 + DYN_H16 * 2)   // 215040 B

__global__ __launch_bounds__(NTH, 1)
void fargan_kernel(const float* __restrict__ prev0,
                   const float* __restrict__ Wfw,     // (64,388)
                   const float* __restrict__ Wfw_g,   // (64,64)
                   const float* __restrict__ Wih1,    // (192,128)
                   const float* __restrict__ Whh1,    // (192,64)
                   const float* __restrict__ Wih2,
                   const float* __restrict__ Whh2,
                   const float* __restrict__ Wih3,
                   const float* __restrict__ Whh3,
                   const float* __restrict__ Wg1,     // (64,64)
                   const float* __restrict__ Wg2,
                   const float* __restrict__ Wg3,
                   const float* __restrict__ Wsg,     // (128,128)
                   const float* __restrict__ Wsd,     // (128,320)
                   const float* __restrict__ Wout,    // (64,128)
                   float* __restrict__ outp)          // (B, 25600)
{
    const int b   = blockIdx.x;
    const int tid = threadIdx.x;
    const int p   = tid & 7;        // 8 threads per row
    const int r0  = tid >> 3;       // 64 rows per pass

    extern __shared__ unsigned char dynraw[];
    float*  sWhh1 = (float*)dynraw;                  // 192x64
    float*  sWhh2 = sWhh1 + 12288;
    float*  sWhh3 = sWhh2 + 12288;
    float*  sWfw2 = sWhh3 + 12288;                   // 64x136 (cols 128..259 of Wfw)
    __half* sWgh  = (__half*)(sWfw2 + 64 * 136);     // [Wg1|Wg2|Wg3|Wfwg], each 64x64

    __shared__ __align__(16) float ring[LPREV];
    __shared__ __align__(16) float st[2][3][S];      // double-buffered GRU states
    __shared__ __align__(16) float subin[136];       // [prev_sub(64) | lookback(68) | pad(4)]
    __shared__ __align__(16) float fwv[S];
    __shared__ __align__(16) float xcat[2 * S];
    __shared__ __align__(16) float skip[5 * S];
    __shared__ __align__(16) float sdv[2 * S];
    __shared__ __align__(16) float sov[2 * S];
    __shared__ __align__(16) float fwp[S];

    // ---- one-time weight staging ----
    for (int i = tid; i < 12288; i += NTH) {
        sWhh1[i] = __ldg(&Whh1[i]);
        sWhh2[i] = __ldg(&Whh2[i]);
        sWhh3[i] = __ldg(&Whh3[i]);
    }
    for (int i = tid; i < 64 * 136; i += NTH) {
        int row = i / 136, col = i % 136;
        sWfw2[i] = (col < 132) ? __ldg(&Wfw[row * 388 + 128 + col]) : 0.f;
    }
    {
        const float* gsrc[4] = { Wg1, Wg2, Wg3, Wfw_g };
        #pragma unroll
        for (int m = 0; m < 4; m++)
            for (int i = tid; i < 4096; i += NTH)
                sWgh[m * 4096 + i] = __float2half(__ldg(&gsrc[m][i]));
    }

    // ---- register weights: Wsg (128x128), Wout (64x128), fp32 ----
    float4 rsg[2][4], rout[4];
    #pragma unroll
    for (int it = 0; it < 2; it++) {
        const float4* w = (const float4*)(Wsg + (r0 + 64 * it) * 128);
        #pragma unroll
        for (int jj = 0; jj < 4; jj++) rsg[it][jj] = __ldg(&w[4 * p + jj]);
    }
    {
        const float4* w = (const float4*)(Wout + r0 * 128);
        #pragma unroll
        for (int jj = 0; jj < 4; jj++) rout[jj] = __ldg(&w[4 * p + jj]);
    }

    // ---- init state ----
    for (int i = tid; i < LPREV; i += NTH) ring[i] = prev0[b * LPREV + i];
    if (tid < 3 * S) st[0][tid >> 6][tid & 63] = 0.f;
    if (tid >= 132 && tid < 136) subin[tid] = 0.f;
    int head = 0;
    int pb = 0;
    __syncthreads();

    const float* WihL[3] = { Wih1, Wih2, Wih3 };
    float* const sWhhL[3] = { sWhh1, sWhh2, sWhh3 };

    for (int tf = 0; tf < NFRAMES; tf++) {
        const int bt = b * NFRAMES + tf;
        const int period = __ldg(&g_period[bt]);

        for (int k = 0; k < 4; k++) {
            // ---- A: build [prev_sub | lookback], stage fwpre, seed skip/xcat tails
            if (tid < 64) {
                float v = ring[(head + 448 + tid) & 511];
                subin[tid] = v;
                skip[256 + tid] = v;
                xcat[64 + tid] = v;
            } else if (tid < 132) {
                int i = tid - 64;
                int idx = LPREV - period + i - 2;
                if (idx >= LPREV) idx -= period;
                subin[tid] = ring[(head + idx) & 511];
            } else if (tid >= 136 && tid < 200) {
                fwp[tid - 136] = __ldg(&g_fwpre[((long)bt * 4 + k) * 64 + tid - 136]);
            }
            __syncthreads();

            // ---- B: fwraw = tanh(Wfw2 @ subin + fwpre)
            float fwreg;
            {
                float4 a = {0.f, 0.f, 0.f, 0.f};
                const float4* w = (const float4*)(sWfw2 + r0 * 136);
                const float4* x = (const float4*)subin;
                #pragma unroll
                for (int j = p; j < 34; j += 8) fma4(a, w[j], x[j]);
                float acc = red8(hsum4(a));
                fwreg = tanhf(acc + fwp[r0]);
                if (p == 0) fwv[r0] = fwreg;
            }
            __syncthreads();

            // ---- C: fw = fwraw * sigm(Wfwg @ fwv)
            {
                uint4 u = ((const uint4*)(sWgh + 3 * 4096))[r0 * 8 + p];
                const float4* x = (const float4*)fwv;
                float acc = red8(dot8h(u, x[2 * p], x[2 * p + 1]));
                fwreg = fwreg * sigm(acc);
                if (p == 0) { xcat[r0] = fwreg; skip[192 + r0] = fwreg; }
            }
            __syncthreads();

            // ---- 3 x (GRU fused + GLU fused) ----
            #pragma unroll
            for (int L = 0; L < 3; L++) {
                const float* sto = st[pb][L];
                float* stn = st[pb ^ 1][L];
                float streg;
                {
                    // Wih (global): rows r0+64*it, 4 float4 chunks each
                    float4 wa[3][4];
                    #pragma unroll
                    for (int it = 0; it < 3; it++) {
                        const float4* w = (const float4*)(WihL[L] + (r0 + (it << 6)) * 128);
                        #pragma unroll
                        for (int jj = 0; jj < 4; jj++) wa[it][jj] = __ldg(&w[p + 8 * jj]);
                    }
                    float4 xv[4];
                    const float4* x = (const float4*)xcat;
                    #pragma unroll
                    for (int jj = 0; jj < 4; jj++) xv[jj] = x[p + 8 * jj];
                    float4 ai[3] = {{0,0,0,0},{0,0,0,0},{0,0,0,0}};
                    #pragma unroll
                    for (int it = 0; it < 3; it++)
                        #pragma unroll
                        for (int jj = 0; jj < 4; jj++) fma4(ai[it], wa[it][jj], xv[jj]);

                    // Whh (smem): 2 float4 chunks each
                    float4 sv0 = ((const float4*)sto)[p];
                    float4 sv1 = ((const float4*)sto)[p + 8];
                    float4 ah[3] = {{0,0,0,0},{0,0,0,0},{0,0,0,0}};
                    #pragma unroll
                    for (int it = 0; it < 3; it++) {
                        const float4* w = (const float4*)(sWhhL[L] + (r0 + (it << 6)) * 64);
                        fma4(ah[it], w[p], sv0);
                        fma4(ah[it], w[p + 8], sv1);
                    }
                    float gi0 = red8(hsum4(ai[0])), gh0 = red8(hsum4(ah[0]));
                    float gi1 = red8(hsum4(ai[1])), gh1 = red8(hsum4(ah[1]));
                    float gi2 = red8(hsum4(ai[2])), gh2 = red8(hsum4(ah[2]));
                    float r = sigm(gi0 + gh0);
                    float z = sigm(gi1 + gh1);
                    float n = tanhf(gi2 + r * gh2);
                    streg = (1.f - z) * n + z * sto[r0];
                    if (p == 0) stn[r0] = streg;
                }
                __syncthreads();
                {
                    // GLU: v = st_new * sigm(Wg @ st_new)
                    uint4 u = ((const uint4*)(sWgh + L * 4096))[r0 * 8 + p];
                    const float4* x = (const float4*)stn;
                    float acc = red8(dot8h(u, x[2 * p], x[2 * p + 1]));
                    float v = streg * sigm(acc);
                    if (p == 0) {
                        skip[64 * L + r0] = v;
                        if (L < 2) xcat[r0] = v;
                    }
                }
                __syncthreads();
            }

            // ---- J: sdv = tanh(Wsd @ skip)  (global, 320 in, 2 row-blocks)
            float sdva[2];
            {
                #pragma unroll
                for (int it = 0; it < 2; it++) {
                    const float4* w = (const float4*)(Wsd + (r0 + 64 * it) * 320);
                    const float4* x = (const float4*)skip;
                    float4 a = {0.f, 0.f, 0.f, 0.f};
                    #pragma unroll
                    for (int jj = 0; jj < 10; jj++) fma4(a, __ldg(&w[p + 8 * jj]), x[p + 8 * jj]);
                    sdva[it] = tanhf(red8(hsum4(a)));
                    if (p == 0) sdv[r0 + 64 * it] = sdva[it];
                }
            }
            __syncthreads();

            // ---- K: sov = sdv * sigm(Wsg @ sdv)  (register weights)
            {
                const float4* x = (const float4*)sdv;
                float4 xr[4];
                #pragma unroll
                for (int jj = 0; jj < 4; jj++) xr[jj] = x[4 * p + jj];
                #pragma unroll
                for (int it = 0; it < 2; it++) {
                    float4 a = {0.f, 0.f, 0.f, 0.f};
                    #pragma unroll
                    for (int jj = 0; jj < 4; jj++) fma4(a, rsg[it][jj], xr[jj]);
                    float acc = red8(hsum4(a));
                    if (p == 0) sov[r0 + 64 * it] = sdva[it] * sigm(acc);
                }
            }
            __syncthreads();

            // ---- L: out = tanh(Wout @ sov); emit + ring update
            {
                const float4* x = (const float4*)sov;
                float4 a = {0.f, 0.f, 0.f, 0.f};
                #pragma unroll
                for (int jj = 0; jj < 4; jj++) fma4(a, rout[jj], x[4 * p + jj]);
                float out = tanhf(red8(hsum4(a)));
                if (p == 0) {
                    outp[(long)b * (NFRAMES * 4 * S) + tf * (4 * S) + k * S + r0] = out;
                    ring[(head + r0) & 511] = out;
                }
            }
            head = (head + 64) & 511;
            pb ^= 1;
            __syncthreads();
        }
    }
}

extern "C" void kernel_launch(void* const* d_in, const int* in_sizes, int n_in,
                              void* d_out, int out_size)
{
    const float* feats = (const float*)d_in[0];
    const float* glob  = (const float*)d_in[1];
    const float* prev0 = (const float*)d_in[2];
    const float* Wc1   = (const float*)d_in[3];
    const float* Wc2   = (const float*)d_in[4];
    const float* Wc3   = (const float*)d_in[5];
    const float* Wfw   = (const float*)d_in[6];
    const float* Wfw_g = (const float*)d_in[7];
    const float* Wih1  = (const float*)d_in[8];
    const float* Whh1  = (const float*)d_in[9];
    const float* Wih2  = (const float*)d_in[10];
    const float* Whh2  = (const float*)d_in[11];
    const float* Wih3  = (const float*)d_in[12];
    const float* Whh3  = (const float*)d_in[13];
    const float* Wg1   = (const float*)d_in[14];
    const float* Wg2   = (const float*)d_in[15];
    const float* Wg3   = (const float*)d_in[16];
    const float* Wsg   = (const float*)d_in[17];
    const float* Wsd   = (const float*)d_in[18];
    const float* Wout  = (const float*)d_in[19];
    float* outp = (float*)d_out;

    static bool attr_set = false;
    if (!attr_set) {
        cudaFuncSetAttribute(fargan_kernel,
                             cudaFuncAttributeMaxDynamicSharedMemorySize, DYN_BYTES);
        attr_set = true;
    }

    build_x_kernel<<<NBT, 64>>>(feats, glob);
    gemm_tanh_kernel<<<dim3(4, 100), 256>>>(Wc1, 0, 256, 256);
    gemm_tanh_kernel<<<dim3(4, 100), 256>>>(Wc2, 1, 256, 256);
    gemm_tanh_kernel<<<dim3(8, 100), 256>>>(Wc3, 2, 512, 256);
    fwpre_kernel<<<NBT, 256>>>(Wfw);
    fargan_kernel<<<BATCH, NTH, DYN_BYTES>>>(prev0,
                                  Wfw, Wfw_g,
                                  Wih1, Whh1, Wih2, Whh2, Wih3, Whh3,
                                  Wg1, Wg2, Wg3, Wsg, Wsd, Wout, outp);
}

// round 5
// speedup vs baseline: 1.5961x; 1.1820x over previous
#include <cuda_runtime.h>
#include <cuda_fp16.h>
#include <math.h>

#define S       64
#define LPREV   512
#define NF      193
#define NFRAMES 100
#define BATCH   64
#define NTH     512
#define NBT     (BATCH * NFRAMES)   // 6400

// ---------------- scratch (static device allocations) ----------------
__device__ float  g_X [NBT * 256];
__device__ float  g_H1[NBT * 256];
__device__ float  g_H2[NBT * 256];
__device__ float  g_C [NBT * 512];
__device__ float  g_fwpre[NBT * 4 * 64];
__device__ int    g_period[NBT];
__device__ __half g_hWsd[128 * 320];

__device__ __forceinline__ float sigm(float x) { return 1.0f / (1.0f + __expf(-x)); }
__device__ __forceinline__ float hsum4(float4 a) { return (a.x + a.y) + (a.z + a.w); }
__device__ __forceinline__ float red8(float v) {
    v += __shfl_xor_sync(0xffffffffu, v, 1);
    v += __shfl_xor_sync(0xffffffffu, v, 2);
    v += __shfl_xor_sync(0xffffffffu, v, 4);
    return v;
}
__device__ __forceinline__ void fma4(float4& a, float4 w, float4 x) {
    a.x = fmaf(w.x, x.x, a.x); a.y = fmaf(w.y, x.y, a.y);
    a.z = fmaf(w.z, x.z, a.z); a.w = fmaf(w.w, x.w, a.w);
}
// dot of 8 fp16 weights (one uint4) with 8 fp32 inputs (two float4)
__device__ __forceinline__ float dot8h(uint4 u, float4 xa, float4 xb) {
    float2 f0 = __half22float2(*reinterpret_cast<__half2*>(&u.x));
    float2 f1 = __half22float2(*reinterpret_cast<__half2*>(&u.y));
    float2 f2 = __half22float2(*reinterpret_cast<__half2*>(&u.z));
    float2 f3 = __half22float2(*reinterpret_cast<__half2*>(&u.w));
    float a = fmaf(f0.x, xa.x, f0.y * xa.y);
    a = fmaf(f1.x, xa.z, a); a = fmaf(f1.y, xa.w, a);
    a = fmaf(f2.x, xb.x, a); a = fmaf(f2.y, xb.y, a);
    a = fmaf(f3.x, xb.z, a); a = fmaf(f3.y, xb.w, a);
    return a;
}
// pack 8 consecutive fp32 -> uint4 of 8 fp16
__device__ __forceinline__ uint4 pack8(const float* __restrict__ s) {
    union { uint4 u; __half2 h[4]; } r;
    r.h[0] = __floats2half2_rn(__ldg(&s[0]), __ldg(&s[1]));
    r.h[1] = __floats2half2_rn(__ldg(&s[2]), __ldg(&s[3]));
    r.h[2] = __floats2half2_rn(__ldg(&s[4]), __ldg(&s[5]));
    r.h[3] = __floats2half2_rn(__ldg(&s[6]), __ldg(&s[7]));
    return r.u;
}

// ---------------- prep kernels ----------------
__global__ void convert_wsd_kernel(const float* __restrict__ Wsd)
{
    int i = blockIdx.x * blockDim.x + threadIdx.x;
    if (i < 128 * 320) g_hWsd[i] = __float2half(Wsd[i]);
}

__global__ void build_x_kernel(const float* __restrict__ feats,
                               const float* __restrict__ glob)
{
    const int bt = blockIdx.x;
    const int b = bt / NFRAMES, t = bt % NFRAMES;
    const float* fb = feats + (long)b * NF * NFRAMES;
    for (int i = threadIdx.x; i < 192; i += blockDim.x)
        g_X[bt * 256 + i] = fb[i * NFRAMES + t];
    for (int i = threadIdx.x; i < 64; i += blockDim.x)
        g_X[bt * 256 + 192 + i] = glob[b * 64 + i];
    if (threadIdx.x == 0)
        g_period[bt] = (int)lrintf(fb[192 * NFRAMES + t]);
}

// C[M,N] = tanh(A[M,K] @ W[N,K]^T); tiles 64x64x64
__global__ __launch_bounds__(256)
void gemm_tanh_kernel(const float* __restrict__ Wt, int layer, int N, int K)
{
    const float* A = (layer == 0) ? g_X : (layer == 1) ? g_H1 : g_H2;
    float*       C = (layer == 0) ? g_H1 : (layer == 1) ? g_H2 : g_C;

    __shared__ float As[64][68];
    __shared__ float Ws[64][68];

    const int tid = threadIdx.x;
    const int m0 = blockIdx.y * 64, n0 = blockIdx.x * 64;
    const int lr = tid >> 2, lc = tid & 3;
    const int ty = tid >> 4, tx = tid & 15;

    float acc[4][4] = {};

    for (int k0 = 0; k0 < K; k0 += 64) {
        const float4* Arow = (const float4*)(A  + (long)(m0 + lr) * K + k0);
        const float4* Wrow = (const float4*)(Wt + (long)(n0 + lr) * K + k0);
        #pragma unroll
        for (int jj = 0; jj < 4; jj++) {
            float4 av = __ldg(&Arow[lc * 4 + jj]);
            float4 wv = __ldg(&Wrow[lc * 4 + jj]);
            int kk = lc * 16 + jj * 4;
            As[kk + 0][lr] = av.x; As[kk + 1][lr] = av.y;
            As[kk + 2][lr] = av.z; As[kk + 3][lr] = av.w;
            Ws[kk + 0][lr] = wv.x; Ws[kk + 1][lr] = wv.y;
            Ws[kk + 2][lr] = wv.z; Ws[kk + 3][lr] = wv.w;
        }
        __syncthreads();
        #pragma unroll
        for (int kk = 0; kk < 64; kk++) {
            float4 a = *(const float4*)&As[kk][ty * 4];
            float4 w = *(const float4*)&Ws[kk][tx * 4];
            acc[0][0] = fmaf(a.x, w.x, acc[0][0]); acc[0][1] = fmaf(a.x, w.y, acc[0][1]);
            acc[0][2] = fmaf(a.x, w.z, acc[0][2]); acc[0][3] = fmaf(a.x, w.w, acc[0][3]);
            acc[1][0] = fmaf(a.y, w.x, acc[1][0]); acc[1][1] = fmaf(a.y, w.y, acc[1][1]);
            acc[1][2] = fmaf(a.y, w.z, acc[1][2]); acc[1][3] = fmaf(a.y, w.w, acc[1][3]);
            acc[2][0] = fmaf(a.z, w.x, acc[2][0]); acc[2][1] = fmaf(a.z, w.y, acc[2][1]);
            acc[2][2] = fmaf(a.z, w.z, acc[2][2]); acc[2][3] = fmaf(a.z, w.w, acc[2][3]);
            acc[3][0] = fmaf(a.w, w.x, acc[3][0]); acc[3][1] = fmaf(a.w, w.y, acc[3][1]);
            acc[3][2] = fmaf(a.w, w.z, acc[3][2]); acc[3][3] = fmaf(a.w, w.w, acc[3][3]);
        }
        __syncthreads();
    }
    #pragma unroll
    for (int i = 0; i < 4; i++)
        #pragma unroll
        for (int j = 0; j < 4; j++)
            C[(long)(m0 + ty * 4 + i) * N + n0 + tx * 4 + j] = tanhf(acc[i][j]);
}

// fwpre[bt][k][j] = Wfw[j,0:128] @ feat2s(bt,k) + Wfw[j,260:388] @ sfw(bt,k)
__global__ __launch_bounds__(256)
void fwpre_kernel(const float* __restrict__ Wfw)
{
    const int bt = blockIdx.x;
    const int t  = bt % NFRAMES;
    const int tid = threadIdx.x;
    __shared__ float sc[512], sp[512];
    for (int i = tid; i < 512; i += 256) {
        sc[i] = g_C[(long)bt * 512 + i];
        sp[i] = (t > 0) ? g_C[(long)(bt - 1) * 512 + i] : 0.f;
    }
    __syncthreads();
    const int p = tid & 3, row = tid >> 2;
    const float* wr = Wfw + row * 388;
    #pragma unroll
    for (int k = 0; k < 4; k++) {
        const float* sfw = (k == 0) ? sp : sc;
        const int ksf = (k == 0) ? 3 : (k - 1);
        float acc = 0.f;
        #pragma unroll 8
        for (int mm = 0; mm < 32; mm++) {
            int m = p * 32 + mm;
            acc = fmaf(__ldg(&wr[m]),       sc[4 * m + k],    acc);
            acc = fmaf(__ldg(&wr[260 + m]), sfw[4 * m + ksf], acc);
        }
        acc += __shfl_xor_sync(0xffffffffu, acc, 1);
        acc += __shfl_xor_sync(0xffffffffu, acc, 2);
        if (p == 0) g_fwpre[((long)bt * 4 + k) * 64 + row] = acc;
    }
}

// ---------------- serial recurrence ----------------

#define DYN_H16   (3 * 192 * 128 + 3 * 192 * 64)   // Wih x3 + Whh x3 = 110592 halfs
#define DYN_BYTES (DYN_H16 * 2)                    // 221184 B

__global__ __launch_bounds__(NTH, 1)
void fargan_kernel(const float* __restrict__ prev0,
                   const float* __restrict__ Wfw,     // (64,388)
                   const float* __restrict__ Wfw_g,   // (64,64)
                   const float* __restrict__ Wih1,    // (192,128)
                   const float* __restrict__ Whh1,    // (192,64)
                   const float* __restrict__ Wih2,
                   const float* __restrict__ Whh2,
                   const float* __restrict__ Wih3,
                   const float* __restrict__ Whh3,
                   const float* __restrict__ Wg1,     // (64,64)
                   const float* __restrict__ Wg2,
                   const float* __restrict__ Wg3,
                   const float* __restrict__ Wsg,     // (128,128)
                   const float* __restrict__ Wout,    // (64,128)
                   float* __restrict__ outp)          // (B, 25600)
{
    const int b   = blockIdx.x;
    const int tid = threadIdx.x;
    const int p   = tid & 7;        // 8 threads per row
    const int r0  = tid >> 3;       // 64 rows per pass

    extern __shared__ __half dynh[];
    __half* sWih = dynh;                 // 3 x 192 x 128
    __half* sWhh = dynh + 3 * 192 * 128; // 3 x 192 x 64

    __shared__ __align__(16) float ring[LPREV];
    __shared__ __align__(16) float st[2][3][S];      // double-buffered GRU states
    __shared__ __align__(16) float subin[136];       // [prev_sub(64) | lookback(68) | pad(4)]
    __shared__ __align__(16) float fwv[S];
    __shared__ __align__(16) float xcat[2 * S];
    __shared__ __align__(16) float skip[5 * S];
    __shared__ __align__(16) float sdv[2 * S];
    __shared__ __align__(16) float sov[2 * S];
    __shared__ __align__(16) float fwp[S];

    // ---- one-time: stage Wih / Whh as fp16 into smem ----
    {
        const float* src[3] = { Wih1, Wih2, Wih3 };
        #pragma unroll
        for (int m = 0; m < 3; m++)
            for (int i = tid; i < 192 * 128; i += NTH)
                sWih[m * 192 * 128 + i] = __float2half(__ldg(&src[m][i]));
        const float* srh[3] = { Whh1, Whh2, Whh3 };
        #pragma unroll
        for (int m = 0; m < 3; m++)
            for (int i = tid; i < 192 * 64; i += NTH)
                sWhh[m * 192 * 64 + i] = __float2half(__ldg(&srh[m][i]));
    }

    // ---- persistent register weight caches ----
    // Wfw2: cols [128,264) of Wfw, row r0, 17 consecutive floats per thread (fp32)
    float rfw2[17];
    #pragma unroll
    for (int i = 0; i < 17; i++) {
        int col = p * 17 + i;   // 0..135 within the 136-col window
        rfw2[i] = (col < 132) ? __ldg(&Wfw[r0 * 388 + 128 + col]) : 0.f;
    }
    // gates (Wg1,Wg2,Wg3,Wfwg): 64x64 fp16, chunk p of 8 per row
    uint4 rgate[4];
    {
        const float* gsrc[4] = { Wg1, Wg2, Wg3, Wfw_g };
        #pragma unroll
        for (int m = 0; m < 4; m++) rgate[m] = pack8(gsrc[m] + r0 * 64 + 8 * p);
    }
    // Wsg: 128x128 fp16, rows r0 and r0+64, chunks p and p+8
    uint4 rsgh[2][2];
    #pragma unroll
    for (int it = 0; it < 2; it++) {
        rsgh[it][0] = pack8(Wsg + (r0 + 64 * it) * 128 + 8 * p);
        rsgh[it][1] = pack8(Wsg + (r0 + 64 * it) * 128 + 8 * (p + 8));
    }
    // Wout: 64x128 fp16, row r0, chunks p and p+8
    uint4 routh[2];
    routh[0] = pack8(Wout + r0 * 128 + 8 * p);
    routh[1] = pack8(Wout + r0 * 128 + 8 * (p + 8));

    // ---- init state ----
    for (int i = tid; i < LPREV; i += NTH) ring[i] = prev0[b * LPREV + i];
    if (tid < 3 * S) st[0][tid >> 6][tid & 63] = 0.f;
    if (tid >= 132 && tid < 136) subin[tid] = 0.f;
    int head = 0;
    int pb = 0;
    __syncthreads();

    for (int tf = 0; tf < NFRAMES; tf++) {
        const int bt = b * NFRAMES + tf;
        const int period = __ldg(&g_period[bt]);

        for (int k = 0; k < 4; k++) {
            // ---- A: build [prev_sub | lookback], stage fwpre, seed tails
            if (tid < 64) {
                float v = ring[(head + 448 + tid) & 511];
                subin[tid] = v;
                skip[256 + tid] = v;
                xcat[64 + tid] = v;
            } else if (tid < 132) {
                int i = tid - 64;
                int idx = LPREV - period + i - 2;
                if (idx >= LPREV) idx -= period;
                subin[tid] = ring[(head + idx) & 511];
            } else if (tid >= 136 && tid < 200) {
                fwp[tid - 136] = __ldg(&g_fwpre[((long)bt * 4 + k) * 64 + tid - 136]);
            }
            __syncthreads();

            // ---- B: fwraw = tanh(Wfw2 @ subin + fwpre)   (register weights)
            float fwreg;
            {
                float a = 0.f;
                #pragma unroll
                for (int i = 0; i < 17; i++)
                    a = fmaf(rfw2[i], subin[p * 17 + i], a);
                fwreg = tanhf(red8(a) + fwp[r0]);
                if (p == 0) fwv[r0] = fwreg;
            }
            __syncthreads();

            // ---- C: fw = fwraw * sigm(Wfwg @ fwv)   (register gate)
            {
                const float4* x = (const float4*)fwv;
                float acc = red8(dot8h(rgate[3], x[2 * p], x[2 * p + 1]));
                fwreg = fwreg * sigm(acc);
                if (p == 0) { xcat[r0] = fwreg; skip[192 + r0] = fwreg; }
            }
            __syncthreads();

            // ---- 3 x (GRU fused + GLU fused), weights in smem fp16 ----
            #pragma unroll
            for (int L = 0; L < 3; L++) {
                const __half* WI = sWih + L * 192 * 128;
                const __half* WH = sWhh + L * 192 * 64;
                const float* sto = st[pb][L];
                float* stn = st[pb ^ 1][L];
                float streg;
                {
                    const float4* x = (const float4*)xcat;
                    float4 xa0 = x[2 * p], xa1 = x[2 * p + 1];
                    float4 xb0 = x[2 * p + 16], xb1 = x[2 * p + 17];
                    float4 sv0 = ((const float4*)sto)[2 * p], sv1 = ((const float4*)sto)[2 * p + 1];
                    float gi[3], gh[3];
                    #pragma unroll
                    for (int it = 0; it < 3; it++) {
                        const uint4* wi = (const uint4*)(WI + (r0 + (it << 6)) * 128);
                        float a = dot8h(wi[p], xa0, xa1) + dot8h(wi[p + 8], xb0, xb1);
                        gi[it] = red8(a);
                        const uint4* wh = (const uint4*)(WH + (r0 + (it << 6)) * 64);
                        gh[it] = red8(dot8h(wh[p], sv0, sv1));
                    }
                    float r = sigm(gi[0] + gh[0]);
                    float z = sigm(gi[1] + gh[1]);
                    float n = tanhf(gi[2] + r * gh[2]);
                    streg = (1.f - z) * n + z * sto[r0];
                    if (p == 0) stn[r0] = streg;
                }
                __syncthreads();
                {
                    const float4* x = (const float4*)stn;
                    float acc = red8(dot8h(rgate[L], x[2 * p], x[2 * p + 1]));
                    float v = streg * sigm(acc);
                    if (p == 0) {
                        skip[64 * L + r0] = v;
                        if (L < 2) xcat[r0] = v;
                    }
                }
                __syncthreads();
            }

            // ---- J: sdv = tanh(Wsd @ skip)   (global fp16, only streamed stage)
            float sdva[2];
            {
                const float4* xs = (const float4*)skip;
                #pragma unroll
                for (int it = 0; it < 2; it++) {
                    const uint4* w = (const uint4*)(g_hWsd + (r0 + (it << 6)) * 320);
                    float a = 0.f;
                    #pragma unroll
                    for (int j = 0; j < 5; j++) {
                        int c = p + 8 * j;
                        a += dot8h(__ldg(&w[c]), xs[2 * c], xs[2 * c + 1]);
                    }
                    sdva[it] = tanhf(red8(a));
                    if (p == 0) sdv[r0 + 64 * it] = sdva[it];
                }
            }
            __syncthreads();

            // ---- K: sov = sdv * sigm(Wsg @ sdv)   (register fp16)
            {
                const float4* x = (const float4*)sdv;
                float4 xa0 = x[2 * p], xa1 = x[2 * p + 1];
                float4 xb0 = x[2 * p + 16], xb1 = x[2 * p + 17];
                #pragma unroll
                for (int it = 0; it < 2; it++) {
                    float acc = dot8h(rsgh[it][0], xa0, xa1) + dot8h(rsgh[it][1], xb0, xb1);
                    acc = red8(acc);
                    if (p == 0) sov[r0 + 64 * it] = sdva[it] * sigm(acc);
                }
            }
            __syncthreads();

            // ---- L: out = tanh(Wout @ sov); emit + ring update   (register fp16)
            {
                const float4* x = (const float4*)sov;
                float acc = dot8h(routh[0], x[2 * p], x[2 * p + 1])
                          + dot8h(routh[1], x[2 * p + 16], x[2 * p + 17]);
                float out = tanhf(red8(acc));
                if (p == 0) {
                    outp[(long)b * (NFRAMES * 4 * S) + tf * (4 * S) + k * S + r0] = out;
                    ring[(head + r0) & 511] = out;
                }
            }
            head = (head + 64) & 511;
            pb ^= 1;
            __syncthreads();
        }
    }
}

extern "C" void kernel_launch(void* const* d_in, const int* in_sizes, int n_in,
                              void* d_out, int out_size)
{
    const float* feats = (const float*)d_in[0];
    const float* glob  = (const float*)d_in[1];
    const float* prev0 = (const float*)d_in[2];
    const float* Wc1   = (const float*)d_in[3];
    const float* Wc2   = (const float*)d_in[4];
    const float* Wc3   = (const float*)d_in[5];
    const float* Wfw   = (const float*)d_in[6];
    const float* Wfw_g = (const float*)d_in[7];
    const float* Wih1  = (const float*)d_in[8];
    const float* Whh1  = (const float*)d_in[9];
    const float* Wih2  = (const float*)d_in[10];
    const float* Whh2  = (const float*)d_in[11];
    const float* Wih3  = (const float*)d_in[12];
    const float* Whh3  = (const float*)d_in[13];
    const float* Wg1   = (const float*)d_in[14];
    const float* Wg2   = (const float*)d_in[15];
    const float* Wg3   = (const float*)d_in[16];
    const float* Wsg   = (const float*)d_in[17];
    const float* Wsd   = (const float*)d_in[18];
    const float* Wout  = (const float*)d_in[19];
    float* outp = (float*)d_out;

    static bool attr_set = false;
    if (!attr_set) {
        cudaFuncSetAttribute(fargan_kernel,
                             cudaFuncAttributeMaxDynamicSharedMemorySize, DYN_BYTES);
        attr_set = true;
    }

    convert_wsd_kernel<<<(128 * 320 + 255) / 256, 256>>>(Wsd);
    build_x_kernel<<<NBT, 64>>>(feats, glob);
    gemm_tanh_kernel<<<dim3(4, 100), 256>>>(Wc1, 0, 256, 256);
    gemm_tanh_kernel<<<dim3(4, 100), 256>>>(Wc2, 1, 256, 256);
    gemm_tanh_kernel<<<dim3(8, 100), 256>>>(Wc3, 2, 512, 256);
    fwpre_kernel<<<NBT, 256>>>(Wfw);
    fargan_kernel<<<BATCH, NTH, DYN_BYTES>>>(prev0,
                                  Wfw, Wfw_g,
                                  Wih1, Whh1, Wih2, Whh2, Wih3, Whh3,
                                  Wg1, Wg2, Wg3, Wsg, Wout, outp);
}